// round 5
// baseline (speedup 1.0000x reference)
#include <cuda_runtime.h>
#include <math.h>

#define S_LEN   4096
#define D_DIM   512
#define K_TOT   1536          // 3 taps * 512
#define MAX_OUT 16384
#define BASE_OUT (MAX_OUT * D_DIM)   // 8388608

// ---------------- device scratch (16B aligned; no allocations allowed) ----------------
__device__ __align__(16) float g_Wt1[K_TOT * D_DIM];   // [(tap*512+i), o]
__device__ __align__(16) float g_Wt2[K_TOT * D_DIM];
__device__ __align__(16) float g_b1[S_LEN * D_DIM];    // conv1 out, then reused for conv2 out
__device__ __align__(16) float g_b2[S_LEN * D_DIM];    // ln1+relu out
__device__ __align__(16) int   g_dur[S_LEN];
__device__ __align__(16) int   g_cum[S_LEN];

// ---------------- weight transpose (both convs): w[o][i][k] -> Wt[(k*512+i)][o] ----------------
__global__ void transpose_w_kernel(const float* __restrict__ w1, const float* __restrict__ w2) {
    int idx = blockIdx.x * blockDim.x + threadIdx.x;
    const int n = K_TOT * D_DIM;
    if (idx >= 2 * n) return;
    const float* w  = (idx < n) ? w1 : w2;
    float*       wt = (idx < n) ? g_Wt1 : g_Wt2;
    int j  = (idx < n) ? idx : idx - n;
    int o  = j & 511;
    int ki = j >> 9;
    int i  = ki & 511;
    int k  = ki >> 9;
    wt[j] = w[o * 1536 + i * 3 + k];
}

// ---------------- conv-as-GEMM: Y[s,o] = sum_{tap,i} X[s-1+tap, i] * Wt[(tap,i), o] + bias[o]
// BM=128, BN=64, BK=16, 256 threads, 8x4 microtile
__global__ __launch_bounds__(256) void conv_gemm_kernel(
    const float* __restrict__ enc, const float* __restrict__ bias, int which) {
    const float* X  = which ? g_b2  : enc;
    const float* Wt = which ? g_Wt2 : g_Wt1;
    float*       Y  = which ? g_b1  : g_b1;   // conv1 -> g_b1 ; conv2 -> g_b1 (reuse)
    float*       Yc = which ? g_b1  : g_b1;
    (void)Yc;

    __shared__ float As[16][132];   // [k][m], padded
    __shared__ float Bs[16][64];    // [k][n]

    const int bm  = blockIdx.y * 128;
    const int bn  = blockIdx.x * 64;
    const int tid = threadIdx.x;
    const int tx  = tid & 15;           // n-group  (0..15) -> 4 cols
    const int ty  = tid >> 4;           // m-group  (0..15) -> 8 rows
    const int ar  = tid >> 1;           // A loader row 0..127
    const int akq = (tid & 1) * 8;      // A loader k-offset 0 or 8
    const int br  = tid >> 4;           // B loader k-row 0..15
    const int bc  = (tid & 15) * 4;     // B loader col 0..60

    float acc[8][4];
    #pragma unroll
    for (int i = 0; i < 8; i++)
        #pragma unroll
        for (int j = 0; j < 4; j++) acc[i][j] = 0.f;

    for (int k0 = 0; k0 < K_TOT; k0 += 16) {
        const int tap = k0 >> 9;        // constant within a chunk (512 % 16 == 0)
        const int i0  = k0 & 511;
        const int s   = bm + ar + tap - 1;
        float4 a0 = make_float4(0.f, 0.f, 0.f, 0.f);
        float4 a1 = make_float4(0.f, 0.f, 0.f, 0.f);
        if (s >= 0 && s < S_LEN) {
            const float* xr = X + (size_t)s * D_DIM + i0 + akq;
            a0 = *reinterpret_cast<const float4*>(xr);
            a1 = *reinterpret_cast<const float4*>(xr + 4);
        }
        As[akq + 0][ar] = a0.x;  As[akq + 1][ar] = a0.y;
        As[akq + 2][ar] = a0.z;  As[akq + 3][ar] = a0.w;
        As[akq + 4][ar] = a1.x;  As[akq + 5][ar] = a1.y;
        As[akq + 6][ar] = a1.z;  As[akq + 7][ar] = a1.w;

        *reinterpret_cast<float4*>(&Bs[br][bc]) =
            *reinterpret_cast<const float4*>(Wt + (size_t)(k0 + br) * D_DIM + bn + bc);
        __syncthreads();

        #pragma unroll
        for (int k = 0; k < 16; k++) {
            float a[8];
            #pragma unroll
            for (int i = 0; i < 8; i++) a[i] = As[k][ty * 8 + i];
            float4 bv = *reinterpret_cast<const float4*>(&Bs[k][tx * 4]);
            #pragma unroll
            for (int i = 0; i < 8; i++) {
                acc[i][0] += a[i] * bv.x;
                acc[i][1] += a[i] * bv.y;
                acc[i][2] += a[i] * bv.z;
                acc[i][3] += a[i] * bv.w;
            }
        }
        __syncthreads();
    }

    const float4 bb = *reinterpret_cast<const float4*>(bias + bn + tx * 4);
    #pragma unroll
    for (int i = 0; i < 8; i++) {
        const int row = bm + ty * 8 + i;
        float4 ov;
        ov.x = acc[i][0] + bb.x;
        ov.y = acc[i][1] + bb.y;
        ov.z = acc[i][2] + bb.z;
        ov.w = acc[i][3] + bb.w;
        *reinterpret_cast<float4*>(Y + (size_t)row * D_DIM + bn + tx * 4) = ov;
    }
}

__device__ __forceinline__ float warp_allsum(float v) {
    #pragma unroll
    for (int o = 16; o > 0; o >>= 1) v += __shfl_xor_sync(0xffffffffu, v, o);
    return v;
}

// ---------------- LN1 + ReLU:  g_b1 -> g_b2   (128 threads / row) ----------------
__global__ __launch_bounds__(128) void ln_relu_kernel(
    const float* __restrict__ G, const float* __restrict__ Bt) {
    const int s   = blockIdx.x;
    const int tid = threadIdx.x;
    __shared__ float red1[4], red2[4];

    float4 v = reinterpret_cast<const float4*>(g_b1 + (size_t)s * D_DIM)[tid];
    float p = warp_allsum(v.x + v.y + v.z + v.w);
    const int lane = tid & 31, wid = tid >> 5;
    if (lane == 0) red1[wid] = p;
    __syncthreads();
    const float mean = (red1[0] + red1[1] + red1[2] + red1[3]) * (1.0f / 512.0f);

    float dx = v.x - mean, dy = v.y - mean, dz = v.z - mean, dw = v.w - mean;
    float q = warp_allsum(dx * dx + dy * dy + dz * dz + dw * dw);
    if (lane == 0) red2[wid] = q;
    __syncthreads();
    const float var = (red2[0] + red2[1] + red2[2] + red2[3]) * (1.0f / 512.0f);
    const float inv = rsqrtf(var + 1e-5f);

    const float4 gv = reinterpret_cast<const float4*>(G)[tid];
    const float4 bv = reinterpret_cast<const float4*>(Bt)[tid];
    float4 o;
    o.x = fmaxf(0.f, dx * inv * gv.x + bv.x);
    o.y = fmaxf(0.f, dy * inv * gv.y + bv.y);
    o.z = fmaxf(0.f, dz * inv * gv.z + bv.z);
    o.w = fmaxf(0.f, dw * inv * gv.w + bv.w);
    reinterpret_cast<float4*>(g_b2 + (size_t)s * D_DIM)[tid] = o;
}

// ---------------- LN2 + ReLU + linear(512->1) + ReLU + floor(+0.5): g_b1 -> g_dur ----------------
__global__ __launch_bounds__(128) void ln2_lin_kernel(
    const float* __restrict__ G, const float* __restrict__ Bt,
    const float* __restrict__ LW, const float* __restrict__ LB) {
    const int s   = blockIdx.x;
    const int tid = threadIdx.x;
    __shared__ float red1[4], red2[4], red3[4];

    float4 v = reinterpret_cast<const float4*>(g_b1 + (size_t)s * D_DIM)[tid];
    float p = warp_allsum(v.x + v.y + v.z + v.w);
    const int lane = tid & 31, wid = tid >> 5;
    if (lane == 0) red1[wid] = p;
    __syncthreads();
    const float mean = (red1[0] + red1[1] + red1[2] + red1[3]) * (1.0f / 512.0f);

    float dx = v.x - mean, dy = v.y - mean, dz = v.z - mean, dw = v.w - mean;
    float q = warp_allsum(dx * dx + dy * dy + dz * dz + dw * dw);
    if (lane == 0) red2[wid] = q;
    __syncthreads();
    const float var = (red2[0] + red2[1] + red2[2] + red2[3]) * (1.0f / 512.0f);
    const float inv = rsqrtf(var + 1e-5f);

    const float4 gv = reinterpret_cast<const float4*>(G)[tid];
    const float4 bv = reinterpret_cast<const float4*>(Bt)[tid];
    float ox = fmaxf(0.f, dx * inv * gv.x + bv.x);
    float oy = fmaxf(0.f, dy * inv * gv.y + bv.y);
    float oz = fmaxf(0.f, dz * inv * gv.z + bv.z);
    float ow = fmaxf(0.f, dw * inv * gv.w + bv.w);

    const float4 lw = reinterpret_cast<const float4*>(LW)[tid];
    float d = warp_allsum(ox * lw.x + oy * lw.y + oz * lw.z + ow * lw.w);
    if (lane == 0) red3[wid] = d;
    __syncthreads();
    if (tid == 0) {
        float pred = fmaxf(0.f, red3[0] + red3[1] + red3[2] + red3[3] + LB[0]);
        g_dur[s] = (int)floorf(pred + 0.5f);
    }
}

// ---------------- cumsum over 4096 ints, single block of 512 threads ----------------
__global__ __launch_bounds__(512) void cumsum_kernel() {
    __shared__ int wsum[16];
    const int tid  = threadIdx.x;
    const int lane = tid & 31, wid = tid >> 5;

    int vals[8];
    int s = 0;
    #pragma unroll
    for (int j = 0; j < 8; j++) { s += g_dur[tid * 8 + j]; vals[j] = s; }

    int x = s;
    #pragma unroll
    for (int off = 1; off < 32; off <<= 1) {
        int y = __shfl_up_sync(0xffffffffu, x, off);
        if (lane >= off) x += y;
    }
    if (lane == 31) wsum[wid] = x;
    __syncthreads();
    if (wid == 0 && lane < 16) {
        int w = wsum[lane];
        #pragma unroll
        for (int off = 1; off < 16; off <<= 1) {
            int y = __shfl_up_sync(0x0000ffffu, w, off);
            if (lane >= off) w += y;
        }
        wsum[lane] = w;
    }
    __syncthreads();
    const int offset = (wid > 0 ? wsum[wid - 1] : 0) + (x - s);
    #pragma unroll
    for (int j = 0; j < 8; j++) g_cum[tid * 8 + j] = vals[j] + offset;
}

// ---------------- expansion: one block per output frame t (fixed-trip bisection) ----------------
__global__ __launch_bounds__(128) void expand_kernel(
    const float* __restrict__ enc, float* __restrict__ out) {
    const int t = blockIdx.x;
    __shared__ int s_idx;
    __shared__ int s_valid;
    if (threadIdx.x == 0) {
        const int total = g_cum[S_LEN - 1];
        // count of cum[i] <= t  (== searchsorted right), fixed 12 steps
        int lo = 0;
        #pragma unroll
        for (int step = 2048; step >= 1; step >>= 1) {
            int cand = lo + step;
            if (cand <= S_LEN && g_cum[cand - 1] <= t) lo = cand;
        }
        s_idx = (lo < S_LEN - 1) ? lo : (S_LEN - 1);
        s_valid = (t < total) ? 1 : 0;
    }
    __syncthreads();
    float4 val = make_float4(0.f, 0.f, 0.f, 0.f);
    if (s_valid)
        val = reinterpret_cast<const float4*>(enc + (size_t)s_idx * D_DIM)[threadIdx.x];
    reinterpret_cast<float4*>(out + (size_t)t * D_DIM)[threadIdx.x] = val;
}

// ---------------- optional output_pos tail (if harness concatenates both outputs) ----------------
__global__ void pos_tail_kernel(float* __restrict__ out, int base, int n) {
    int i = blockIdx.x * blockDim.x + threadIdx.x;
    if (i < n) out[base + i] = (float)((i % MAX_OUT) + 1);
}

// ---------------- launch ----------------
extern "C" void kernel_launch(void* const* d_in, const int* in_sizes, int n_in,
                              void* d_out, int out_size) {
    const float* enc = (const float*)d_in[0];
    const float* c1w = (const float*)d_in[1];
    const float* c1b = (const float*)d_in[2];
    const float* g1  = (const float*)d_in[3];
    const float* b1  = (const float*)d_in[4];
    const float* c2w = (const float*)d_in[5];
    const float* c2b = (const float*)d_in[6];
    const float* g2  = (const float*)d_in[7];
    const float* b2  = (const float*)d_in[8];
    const float* lw  = (const float*)d_in[9];
    const float* lb  = (const float*)d_in[10];
    float* out = (float*)d_out;

    // 1) transpose both conv weights
    {
        int n = 2 * K_TOT * D_DIM;
        transpose_w_kernel<<<(n + 255) / 256, 256>>>(c1w, c2w);
    }

    dim3 ggrid(D_DIM / 64, S_LEN / 128);   // (8, 32)
    // 2) conv1 (GEMM)  enc -> g_b1
    conv_gemm_kernel<<<ggrid, 256>>>(enc, c1b, 0);
    // 3) LN1 + ReLU    g_b1 -> g_b2
    ln_relu_kernel<<<S_LEN, 128>>>(g1, b1);
    // 4) conv2 (GEMM)  g_b2 -> g_b1
    conv_gemm_kernel<<<ggrid, 256>>>(enc, c2b, 1);
    // 5) LN2 + ReLU + linear + duration  g_b1 -> g_dur
    ln2_lin_kernel<<<S_LEN, 128>>>(g2, b2, lw, lb);
    // 6) cumsum
    cumsum_kernel<<<1, 512>>>();
    // 7) expand / gather (frame count clamped by out_size)
    int frames = out_size / D_DIM;
    if (frames > MAX_OUT) frames = MAX_OUT;
    if (frames > 0)
        expand_kernel<<<frames, 128>>>(enc, out);
    // 8) optional second-output tail (output_pos = 1..MAX_OUT) if buffer extends past frames
    int base = frames * D_DIM;
    if (out_size > base) {
        int extra = out_size - base;
        pos_tail_kernel<<<(extra + 255) / 256, 256>>>(out, base, extra);
    }
}